// round 3
// baseline (speedup 1.0000x reference)
#include <cuda_runtime.h>
#include <math.h>

// Problem: N=50000 nodes, D=128 feats, E=800000 edges.
// out = support @ (theta*W + (1-theta)*I) + x,  support = (1-a)*SpMM(adj,x) + a*h0
#define D 128
#define MAX_N 50000
#define EPB 512        // edges per block in SpMM
#define MTILE 32       // rows per block in GEMM

// Scratch (no allocation allowed): support [N,D]; W' packed [k/2][col][2]
__device__ float g_support[MAX_N * D];
__device__ float g_wpp[D * D];

__device__ __forceinline__ void fma2(unsigned long long& d,
                                     unsigned long long a,
                                     unsigned long long b) {
    asm("fma.rn.f32x2 %0, %1, %2, %0;" : "+l"(d) : "l"(a), "l"(b));
}

// ---------------------------------------------------------------------------
// Kernel 1: W'[k][c] = theta*W[k][c] + (1-theta)*(k==c), packed pairs along k.
// g_wpp[(k>>1)*2D + c*2 + (k&1)]
// ---------------------------------------------------------------------------
__global__ void prep_wp_kernel(const float* __restrict__ w,
                               const float* __restrict__ lamda_p,
                               const int* __restrict__ layer_p) {
    int k = blockIdx.x;
    int c = threadIdx.x;
    float li = (float)layer_p[0];
    float theta = logf(lamda_p[0] / li + 1.0f);
    float v = theta * w[k * D + c];
    if (k == c) v += 1.0f - theta;
    g_wpp[(k >> 1) * (2 * D) + c * 2 + (k & 1)] = v;
}

// ---------------------------------------------------------------------------
// Kernel 2: support = alpha * h0
// ---------------------------------------------------------------------------
__global__ void init_kernel(const float4* __restrict__ h0,
                            const float* __restrict__ alpha_p, int n4) {
    int i = blockIdx.x * blockDim.x + threadIdx.x;
    if (i < n4) {
        float a = alpha_p[0];
        float4 h = h0[i];
        float4 r;
        r.x = a * h.x; r.y = a * h.y; r.z = a * h.z; r.w = a * h.w;
        ((float4*)g_support)[i] = r;
    }
}

// ---------------------------------------------------------------------------
// Kernel 3: support += (1-alpha) * vals[e] * x[cols[e], :]
// Rows sorted -> register accumulation, atomic flush on row change.
// Software-pipelined: 8 gathers preloaded per chunk (MLP=8).
// ---------------------------------------------------------------------------
__global__ void __launch_bounds__(128) spmm_kernel(
    const float* __restrict__ x,
    const int* __restrict__ rows,
    const int* __restrict__ cols,
    const float* __restrict__ vals,
    const float* __restrict__ alpha_p,
    int E) {
    __shared__ int   s_r[EPB];
    __shared__ int   s_c[EPB];
    __shared__ float s_v[EPB];

    int t = threadIdx.x;
    int e0 = blockIdx.x * EPB;
    int ecnt = E - e0;
    if (ecnt > EPB) ecnt = EPB;

    for (int i = t; i < ecnt; i += 128) {
        s_r[i] = rows[e0 + i];
        s_c[i] = cols[e0 + i];
        s_v[i] = vals[e0 + i];
    }
    __syncthreads();

    float coef = 1.0f - alpha_p[0];
    float acc = 0.0f;
    int cur = s_r[0];

    for (int i0 = 0; i0 < ecnt; i0 += 8) {
        float xv[8];
        #pragma unroll
        for (int j = 0; j < 8; j++) {
            int i = i0 + j;
            xv[j] = (i < ecnt) ? s_v[i] * __ldg(&x[(size_t)s_c[i] * D + t]) : 0.0f;
        }
        #pragma unroll
        for (int j = 0; j < 8; j++) {
            int i = i0 + j;
            if (i < ecnt) {
                int r = s_r[i];
                if (r != cur) {                       // warp-uniform branch
                    atomicAdd(&g_support[(size_t)cur * D + t], coef * acc);
                    acc = 0.0f;
                    cur = r;
                }
                acc += xv[j];
            }
        }
    }
    atomicAdd(&g_support[(size_t)cur * D + t], coef * acc);
}

// ---------------------------------------------------------------------------
// Kernel 4: out = support @ W' + x   (packed-fp32 FFMA2 along k)
// blockDim=128 (thread t = output column t), MTILE=32 rows/block.
// S tile in 16KB static smem (broadcast LDS.128); W' packed, 64-bit LDG (L1).
// acc[i] is an f32x2 pair of partial sums; final = lo + hi.
// ---------------------------------------------------------------------------
__global__ void __launch_bounds__(128) gemm_kernel(
    const float* __restrict__ x,
    float* __restrict__ out,
    int n) {
    __shared__ float S_s[MTILE * D];     // 16 KB

    int t = threadIdx.x;
    int m0 = blockIdx.x * MTILE;
    int rows = n - m0;
    if (rows > MTILE) rows = MTILE;

    // stage support tile (float4 coalesced)
    const float4* ssrc = (const float4*)(g_support + (size_t)m0 * D);
    float4* sdst = (float4*)S_s;
    for (int i = t; i < rows * (D / 4); i += 128) sdst[i] = ssrc[i];
    __syncthreads();

    unsigned long long acc[MTILE];
    #pragma unroll
    for (int i = 0; i < MTILE; i++) acc[i] = 0ull;

    const unsigned long long* W2 = (const unsigned long long*)g_wpp; // [kpair*128 + col]
    const ulonglong2* S2 = (const ulonglong2*)S_s;                   // row i, quad q: i*32+q

    #pragma unroll 1
    for (int kq = 0; kq < D / 2; kq += 2) {          // two k-pairs (4 k) per iter
        unsigned long long w0 = __ldg(&W2[kq * D + t]);
        unsigned long long w1 = __ldg(&W2[(kq + 1) * D + t]);
        int q = kq >> 1;
        #pragma unroll
        for (int i = 0; i < MTILE; i++) {
            ulonglong2 s = S2[i * (D / 4) + q];      // broadcast across warp
            fma2(acc[i], s.x, w0);
            fma2(acc[i], s.y, w1);
        }
    }

    const float* xb = x + (size_t)m0 * D;
    for (int i = 0; i < rows; i++) {
        unsigned lo = (unsigned)(acc[i] & 0xffffffffull);
        unsigned hi = (unsigned)(acc[i] >> 32);
        float v = __uint_as_float(lo) + __uint_as_float(hi);
        out[(size_t)(m0 + i) * D + t] = v + xb[i * D + t];
    }
}

// ---------------------------------------------------------------------------
// Inputs (metadata order): x, h0, weight, lamda, alpha, adj_rows, adj_cols,
//                          adj_vals, layer_idx
// ---------------------------------------------------------------------------
extern "C" void kernel_launch(void* const* d_in, const int* in_sizes, int n_in,
                              void* d_out, int out_size) {
    const float* x     = (const float*)d_in[0];
    const float* h0    = (const float*)d_in[1];
    const float* w     = (const float*)d_in[2];
    const float* lamda = (const float*)d_in[3];
    const float* alpha = (const float*)d_in[4];
    const int*   arows = (const int*)d_in[5];
    const int*   acols = (const int*)d_in[6];
    const float* avals = (const float*)d_in[7];
    const int*   layer = (const int*)d_in[8];

    int ND = in_sizes[0];        // N * 128
    int n  = ND / D;             // N
    int E  = in_sizes[5];        // edge count
    float* out = (float*)d_out;

    prep_wp_kernel<<<D, D>>>(w, lamda, layer);

    int n4 = ND / 4;
    init_kernel<<<(n4 + 255) / 256, 256>>>((const float4*)h0, alpha, n4);

    spmm_kernel<<<(E + EPB - 1) / EPB, 128>>>(x, arows, acols, avals, alpha, E);

    gemm_kernel<<<(n + MTILE - 1) / MTILE, 128>>>(x, out, n);
}

// round 4
// speedup vs baseline: 1.3008x; 1.3008x over previous
#include <cuda_runtime.h>
#include <math.h>

// GCNII layer: out = support @ (theta*W + (1-theta)*I) + x
//              support = (1-alpha)*SpMM(adj, x) + alpha*h0
// N=50000, D=128, E=800000, rows sorted.
#define D 128
#define RTILE 64     // rows per block

// W' packed pairs along k: g_wpp[kq*256 + col*2 + (k&1)]
__device__ float g_wpp[D * D];

__device__ __forceinline__ void fma2(unsigned long long& d,
                                     unsigned long long a,
                                     unsigned long long b) {
    asm("fma.rn.f32x2 %0, %1, %2, %0;" : "+l"(d) : "l"(a), "l"(b));
}

// ---------------------------------------------------------------------------
// W'[k][c] = theta*W[k][c] + (1-theta)*(k==c), packed k-pairs.
// ---------------------------------------------------------------------------
__global__ void prep_wp_kernel(const float* __restrict__ w,
                               const float* __restrict__ lamda_p,
                               const int* __restrict__ layer_p) {
    int k = blockIdx.x;
    int c = threadIdx.x;
    float li = (float)layer_p[0];
    float theta = logf(lamda_p[0] / li + 1.0f);
    float v = theta * w[k * D + c];
    if (k == c) v += 1.0f - theta;
    g_wpp[(k >> 1) * (2 * D) + c * 2 + (k & 1)] = v;
}

// ---------------------------------------------------------------------------
// Fused: per block of 64 rows: init S=alpha*h0 in smem -> edge gather with
// smem atomics -> register-tiled FFMA2 GEMM -> +x residual -> out.
// ---------------------------------------------------------------------------
__global__ void __launch_bounds__(256) fused_kernel(
    const float* __restrict__ x,
    const float* __restrict__ h0,
    const int*   __restrict__ rows,
    const int*   __restrict__ cols,
    const float* __restrict__ vals,
    const float* __restrict__ alpha_p,
    float* __restrict__ out,
    int n, int E) {
    __shared__ float S[RTILE * D];   // 32 KB

    int tid = threadIdx.x;
    int m0 = blockIdx.x * RTILE;
    int nrows = n - m0; if (nrows > RTILE) nrows = RTILE;
    float alpha = __ldg(alpha_p);
    float coef = 1.0f - alpha;

    // --- edge range for this row tile (rows sorted; redundant per-thread) ---
    int lo = 0, hi = E;
    while (lo < hi) { int mid = (lo + hi) >> 1; if (__ldg(&rows[mid]) < m0) lo = mid + 1; else hi = mid; }
    int e_start = lo;
    hi = E;
    while (lo < hi) { int mid = (lo + hi) >> 1; if (__ldg(&rows[mid]) < m0 + RTILE) lo = mid + 1; else hi = mid; }
    int e_end = lo;

    // --- init S = alpha * h0 (zeros on pad rows) ---
    float4* S4 = (float4*)S;
    const float4* h04 = (const float4*)(h0 + (size_t)m0 * D);
    #pragma unroll
    for (int i = tid; i < RTILE * (D / 4); i += 256) {
        float4 v = make_float4(0.f, 0.f, 0.f, 0.f);
        if ((i >> 5) < nrows) {
            float4 h = h04[i];
            v.x = alpha * h.x; v.y = alpha * h.y; v.z = alpha * h.z; v.w = alpha * h.w;
        }
        S4[i] = v;
    }
    __syncthreads();

    // --- gather: 1 warp = 1 contiguous edge stream, float4 per lane ---
    int wid = tid >> 5, lane = tid & 31;
    int ne = e_end - e_start;
    int per = (ne + 7) >> 3;
    int a = e_start + wid * per;
    int b = a + per; if (b > e_end) b = e_end;
    int fo = lane * 4;

    float4 acc = make_float4(0.f, 0.f, 0.f, 0.f);
    int cur = -1;

    auto flush = [&]() {
        if (cur >= 0) {
            float* p = &S[(cur - m0) * D + fo];
            atomicAdd(p + 0, coef * acc.x);
            atomicAdd(p + 1, coef * acc.y);
            atomicAdd(p + 2, coef * acc.z);
            atomicAdd(p + 3, coef * acc.w);
        }
    };
    auto step = [&](int r, float v, float4 xv) {
        if (r != cur) { flush(); cur = r; acc = make_float4(0.f, 0.f, 0.f, 0.f); }
        acc.x = fmaf(v, xv.x, acc.x);
        acc.y = fmaf(v, xv.y, acc.y);
        acc.z = fmaf(v, xv.z, acc.z);
        acc.w = fmaf(v, xv.w, acc.w);
    };

    int e = a;
    for (; e + 4 <= b; e += 4) {
        int r0 = __ldg(&rows[e]),     r1 = __ldg(&rows[e + 1]);
        int r2 = __ldg(&rows[e + 2]), r3 = __ldg(&rows[e + 3]);
        int c0 = __ldg(&cols[e]),     c1 = __ldg(&cols[e + 1]);
        int c2 = __ldg(&cols[e + 2]), c3 = __ldg(&cols[e + 3]);
        float v0 = __ldg(&vals[e]),     v1 = __ldg(&vals[e + 1]);
        float v2 = __ldg(&vals[e + 2]), v3 = __ldg(&vals[e + 3]);
        float4 x0 = *(const float4*)&x[(size_t)c0 * D + fo];
        float4 x1 = *(const float4*)&x[(size_t)c1 * D + fo];
        float4 x2 = *(const float4*)&x[(size_t)c2 * D + fo];
        float4 x3 = *(const float4*)&x[(size_t)c3 * D + fo];
        step(r0, v0, x0); step(r1, v1, x1); step(r2, v2, x2); step(r3, v3, x3);
    }
    for (; e < b; e++) {
        int r = __ldg(&rows[e]);
        int c = __ldg(&cols[e]);
        float v = __ldg(&vals[e]);
        float4 xv = *(const float4*)&x[(size_t)c * D + fo];
        step(r, v, xv);
    }
    flush();
    __syncthreads();

    // --- GEMM: thread (lane=tx, wid=ty) computes rows 8*ty..+7, cols tx+32j ---
    unsigned long long accm[8][4];
    #pragma unroll
    for (int i = 0; i < 8; i++)
        #pragma unroll
        for (int j = 0; j < 4; j++) accm[i][j] = 0ull;

    const unsigned long long* W2 = (const unsigned long long*)g_wpp;  // [kq*128 + col]
    int tx = lane, ty = wid;

    #pragma unroll 1
    for (int q2 = 0; q2 < D / 4; q2++) {        // 4 k-values per iter
        unsigned long long w0[4], w1[4];
        #pragma unroll
        for (int j = 0; j < 4; j++) {
            w0[j] = __ldg(&W2[(2 * q2) * D + tx + 32 * j]);
            w1[j] = __ldg(&W2[(2 * q2 + 1) * D + tx + 32 * j]);
        }
        #pragma unroll
        for (int i = 0; i < 8; i++) {
            ulonglong2 s = *(const ulonglong2*)&S[(8 * ty + i) * D + 4 * q2];  // broadcast
            #pragma unroll
            for (int j = 0; j < 4; j++) {
                fma2(accm[i][j], s.x, w0[j]);
                fma2(accm[i][j], s.y, w1[j]);
            }
        }
    }

    // --- epilogue: lo+hi halves, + x residual ---
    #pragma unroll
    for (int i = 0; i < 8; i++) {
        int r = 8 * ty + i;
        if (r < nrows) {
            const float* xr = x + (size_t)(m0 + r) * D;
            float* orow = out + (size_t)(m0 + r) * D;
            #pragma unroll
            for (int j = 0; j < 4; j++) {
                int c = tx + 32 * j;
                unsigned lo32 = (unsigned)(accm[i][j] & 0xffffffffull);
                unsigned hi32 = (unsigned)(accm[i][j] >> 32);
                orow[c] = __uint_as_float(lo32) + __uint_as_float(hi32) + xr[c];
            }
        }
    }
}

// ---------------------------------------------------------------------------
// Inputs: x, h0, weight, lamda, alpha, adj_rows, adj_cols, adj_vals, layer_idx
// ---------------------------------------------------------------------------
extern "C" void kernel_launch(void* const* d_in, const int* in_sizes, int n_in,
                              void* d_out, int out_size) {
    const float* x     = (const float*)d_in[0];
    const float* h0    = (const float*)d_in[1];
    const float* w     = (const float*)d_in[2];
    const float* lamda = (const float*)d_in[3];
    const float* alpha = (const float*)d_in[4];
    const int*   arows = (const int*)d_in[5];
    const int*   acols = (const int*)d_in[6];
    const float* avals = (const float*)d_in[7];
    const int*   layer = (const int*)d_in[8];

    int ND = in_sizes[0];
    int n  = ND / D;
    int E  = in_sizes[5];
    float* out = (float*)d_out;

    prep_wp_kernel<<<D, D>>>(w, lamda, layer);
    fused_kernel<<<(n + RTILE - 1) / RTILE, 256>>>(x, h0, arows, acols, avals,
                                                   alpha, out, n, E);
}

// round 5
// speedup vs baseline: 1.3936x; 1.0714x over previous
#include <cuda_runtime.h>
#include <math.h>

// GCNII layer: out = support @ (theta*W + (1-theta)*I) + x
//              support = (1-alpha)*SpMM(adj, x) + alpha*h0
// N=50000, D=128, E=800000, rows sorted.
#define D 128
#define RTILE 32       // rows per block
#define CHUNK 512      // edges staged in smem per chunk

// W' packed pairs along k: g_wpp[(k>>1)*256 + col*2 + (k&1)]
__device__ float g_wpp[D * D];

__device__ __forceinline__ void fma2(unsigned long long& d,
                                     unsigned long long a,
                                     unsigned long long b) {
    asm("fma.rn.f32x2 %0, %1, %2, %0;" : "+l"(d) : "l"(a), "l"(b));
}

__global__ void prep_wp_kernel(const float* __restrict__ w,
                               const float* __restrict__ lamda_p,
                               const int* __restrict__ layer_p) {
    int k = blockIdx.x;
    int c = threadIdx.x;
    float li = (float)layer_p[0];
    float theta = logf(lamda_p[0] / li + 1.0f);
    float v = theta * w[k * D + c];
    if (k == c) v += 1.0f - theta;
    g_wpp[(k >> 1) * (2 * D) + c * 2 + (k & 1)] = v;
}

// ---------------------------------------------------------------------------
// Fused per 32-row tile: S = alpha*h0 -> smem-staged edge gather (smem atomics)
// -> register-tiled FFMA2 GEMM -> + x residual.
// ---------------------------------------------------------------------------
__global__ void __launch_bounds__(256, 3) fused_kernel(
    const float* __restrict__ x,
    const float* __restrict__ h0,
    const int*   __restrict__ rows,
    const int*   __restrict__ cols,
    const float* __restrict__ vals,
    const float* __restrict__ alpha_p,
    float* __restrict__ out,
    int n, int E) {
    __shared__ float S[RTILE * D];       // 16 KB
    __shared__ int   s_pk[CHUNK];        // (row_local<<17)|col
    __shared__ float s_v[CHUNK];

    int tid = threadIdx.x;
    int wid = tid >> 5, lane = tid & 31;
    int m0 = blockIdx.x * RTILE;
    int nrows = n - m0; if (nrows > RTILE) nrows = RTILE;
    float alpha = __ldg(alpha_p);
    float coef = 1.0f - alpha;

    // --- edge range for this tile (rows sorted) ---
    int lo = 0, hi = E;
    while (lo < hi) { int mid = (lo + hi) >> 1; if (__ldg(&rows[mid]) < m0) lo = mid + 1; else hi = mid; }
    int e_start = lo;
    hi = E;
    while (lo < hi) { int mid = (lo + hi) >> 1; if (__ldg(&rows[mid]) < m0 + RTILE) lo = mid + 1; else hi = mid; }
    int e_end = lo;

    // --- S = alpha * h0 (zero on pad rows) ---
    float4* S4 = (float4*)S;
    const float4* h04 = (const float4*)(h0 + (size_t)m0 * D);
    #pragma unroll
    for (int i = tid; i < RTILE * (D / 4); i += 256) {
        float4 v = make_float4(0.f, 0.f, 0.f, 0.f);
        if ((i >> 5) < nrows) {
            float4 h = h04[i];
            v.x = alpha * h.x; v.y = alpha * h.y; v.z = alpha * h.z; v.w = alpha * h.w;
        }
        S4[i] = v;
    }

    // --- gather: chunks staged in smem; 8-deep x prefetch per thread ---
    int fo = lane * 4;
    float4 acc = make_float4(0.f, 0.f, 0.f, 0.f);
    int cur = -1;   // local row index

    for (int cs = e_start; cs < e_end; cs += CHUNK) {
        int cn = e_end - cs; if (cn > CHUNK) cn = CHUNK;
        __syncthreads();
        for (int i = tid; i < cn; i += 256) {
            int r = __ldg(&rows[cs + i]) - m0;
            int c = __ldg(&cols[cs + i]);
            s_pk[i] = (r << 17) | c;
            s_v[i]  = __ldg(&vals[cs + i]);
        }
        __syncthreads();

        int per = (cn + 7) >> 3;
        int a = wid * per;
        int b = a + per; if (b > cn) b = cn;

        for (int i0 = a; i0 < b; i0 += 8) {
            float4 xv[8]; float vv[8]; int rr[8];
            #pragma unroll
            for (int j = 0; j < 8; j++) {
                int i = i0 + j;
                if (i < b) {
                    int pk = s_pk[i];
                    rr[j] = pk >> 17;
                    vv[j] = s_v[i];
                    xv[j] = *(const float4*)&x[(size_t)(pk & 0x1FFFF) * D + fo];
                } else rr[j] = -1;
            }
            #pragma unroll
            for (int j = 0; j < 8; j++) {
                if (rr[j] >= 0) {
                    if (rr[j] != cur) {
                        if (cur >= 0) {
                            float* p = &S[cur * D + fo];
                            atomicAdd(p + 0, coef * acc.x);
                            atomicAdd(p + 1, coef * acc.y);
                            atomicAdd(p + 2, coef * acc.z);
                            atomicAdd(p + 3, coef * acc.w);
                        }
                        cur = rr[j];
                        acc = make_float4(0.f, 0.f, 0.f, 0.f);
                    }
                    acc.x = fmaf(vv[j], xv[j].x, acc.x);
                    acc.y = fmaf(vv[j], xv[j].y, acc.y);
                    acc.z = fmaf(vv[j], xv[j].z, acc.z);
                    acc.w = fmaf(vv[j], xv[j].w, acc.w);
                }
            }
        }
    }
    if (cur >= 0) {
        float* p = &S[cur * D + fo];
        atomicAdd(p + 0, coef * acc.x);
        atomicAdd(p + 1, coef * acc.y);
        atomicAdd(p + 2, coef * acc.z);
        atomicAdd(p + 3, coef * acc.w);
    }
    __syncthreads();

    // --- GEMM: warp ty owns rows 4*ty..4*ty+3; lane tx owns cols tx+32j ---
    unsigned long long accm[4][4];
    #pragma unroll
    for (int i = 0; i < 4; i++)
        #pragma unroll
        for (int j = 0; j < 4; j++) accm[i][j] = 0ull;

    const unsigned long long* W2 = (const unsigned long long*)g_wpp;  // [kq*128 + col]
    int tx = lane, ty = wid;

    #pragma unroll 1
    for (int q2 = 0; q2 < D / 4; q2++) {        // 4 k per iter
        unsigned long long w0[4], w1[4];
        #pragma unroll
        for (int j = 0; j < 4; j++) {
            w0[j] = __ldg(&W2[(2 * q2) * D + tx + 32 * j]);
            w1[j] = __ldg(&W2[(2 * q2 + 1) * D + tx + 32 * j]);
        }
        #pragma unroll
        for (int i = 0; i < 4; i++) {
            ulonglong2 s = *(const ulonglong2*)&S[(4 * ty + i) * D + 4 * q2];  // broadcast
            #pragma unroll
            for (int j = 0; j < 4; j++) {
                fma2(accm[i][j], s.x, w0[j]);
                fma2(accm[i][j], s.y, w1[j]);
            }
        }
    }

    // --- epilogue: sum pair halves, + x residual ---
    #pragma unroll
    for (int i = 0; i < 4; i++) {
        int r = 4 * ty + i;
        if (r < nrows) {
            const float* xr = x + (size_t)(m0 + r) * D;
            float* orow = out + (size_t)(m0 + r) * D;
            #pragma unroll
            for (int j = 0; j < 4; j++) {
                int c = tx + 32 * j;
                unsigned lo32 = (unsigned)(accm[i][j] & 0xffffffffull);
                unsigned hi32 = (unsigned)(accm[i][j] >> 32);
                orow[c] = __uint_as_float(lo32) + __uint_as_float(hi32) + xr[c];
            }
        }
    }
}

// Inputs: x, h0, weight, lamda, alpha, adj_rows, adj_cols, adj_vals, layer_idx
extern "C" void kernel_launch(void* const* d_in, const int* in_sizes, int n_in,
                              void* d_out, int out_size) {
    const float* x     = (const float*)d_in[0];
    const float* h0    = (const float*)d_in[1];
    const float* w     = (const float*)d_in[2];
    const float* lamda = (const float*)d_in[3];
    const float* alpha = (const float*)d_in[4];
    const int*   arows = (const int*)d_in[5];
    const int*   acols = (const int*)d_in[6];
    const float* avals = (const float*)d_in[7];
    const int*   layer = (const int*)d_in[8];

    int ND = in_sizes[0];
    int n  = ND / D;
    int E  = in_sizes[5];
    float* out = (float*)d_out;

    prep_wp_kernel<<<D, D>>>(w, lamda, layer);
    fused_kernel<<<(n + RTILE - 1) / RTILE, 256>>>(x, h0, arows, acols, avals,
                                                   alpha, out, n, E);
}